// round 7
// baseline (speedup 1.0000x reference)
#include <cuda_runtime.h>

#define CUT  14
#define DIM  2744          // 14^3
#define SECT 1834          // sum over sectors of c(s)^2
#define NT   448           // evolve threads per CTA

// ---------------- persistent device scratch (no allocs allowed) ----------------
__device__ float2 g_bs[24][SECT];        // 24 BS gates, sector-packed, TRANSPOSED ([u][cell])
__device__ float2 g_sng[24][CUT*CUT];    // 24 combined single-mode gates ([a][t])
__device__ float  g_dvec[2][1024][3][CUT]; // initial displacement vectors (real)

// ================= gate precompute: fp32 expm (s=8, terms=12, banded Taylor) =================
__global__ void __launch_bounds__(196) gates_kernel(
    const float* __restrict__ th1, const float* __restrict__ ph1,
    const float* __restrict__ vph1, const float* __restrict__ rr,
    const float* __restrict__ phr, const float* __restrict__ th2,
    const float* __restrict__ ph2, const float* __restrict__ vph2,
    const float* __restrict__ aa, const float* __restrict__ pha,
    const float* __restrict__ kk)
{
  __shared__ float2 Bm[196], Ta[196], Tb[196], Ot[196];
  const int tid = threadIdx.x;
  const int i = tid / CUT, j = tid % CUT;
  const int task = blockIdx.x;

  int c = CUT, s = 0, pm = 0, gid = -1;
  double2 h = make_double2(0.0, 0.0);

  if (task < 648) {
    gid = task / 27; s = task % 27;
    pm = (s < CUT) ? 0 : s - (CUT-1);
    c  = (s < CUT) ? s + 1 : 2*CUT - 1 - s;
    int circ = gid / 12, rem = gid % 12;
    int l = rem / 6, w = (rem / 3) % 2, p = rem % 3;
    int pi = (circ*2 + l)*3 + p;
    double th = (double)((w ? th2 : th1)[pi]);
    double ph = (double)((w ? ph2 : ph1)[pi]);
    if (i < c && j < c) {
      int P = pm + i, Q = s - P;
      if (j == i - 1) {            // theta*e^{i phi} * sqrt(P*(Q+1))
        double mag = th * sqrt((double)P * (double)(Q + 1));
        h.x = mag * cos(ph); h.y = mag * sin(ph);
      } else if (j == i + 1) {     // -theta*e^{-i phi} * sqrt((P+1)*Q)
        double mag = th * sqrt((double)(P + 1) * (double)Q);
        h.x = -mag * cos(ph); h.y = mag * sin(ph);
      }
    }
  } else {
    int u = task - 648;
    int circ = u / 12, rem = u % 12;
    int l = rem / 6, w = (rem / 3) % 2, m = rem % 3;
    int pi = (circ*2 + l)*3 + m;
    if (w == 0) {  // squeeze
      double rv = (double)rr[pi], pv = (double)phr[pi];
      double zr = rv*cos(pv), zi = rv*sin(pv);
      if (j == i + 2) {
        double mag = 0.5*sqrt((double)(i+1)*(double)(i+2));
        h.x = mag*zr; h.y = -mag*zi;
      } else if (i == j + 2) {
        double mag = 0.5*sqrt((double)(j+1)*(double)(j+2));
        h.x = -mag*zr; h.y = -mag*zi;
      }
    } else {       // disp
      double av = (double)aa[pi], pv = (double)pha[pi];
      double ar = av*cos(pv), ai = av*sin(pv);
      if (i == j + 1) {
        double mag = sqrt((double)(j+1));
        h.x = mag*ar; h.y = mag*ai;
      } else if (j == i + 1) {
        double mag = sqrt((double)(i+1));
        h.x = -mag*ar; h.y = mag*ai;
      }
    }
  }

  const bool act = (i < c && j < c);
  const double sc = 1.0/256.0;   // 2^-8
  Bm[tid] = make_float2((float)(h.x*sc), (float)(h.y*sc));
  float idv = (act && i == j) ? 1.0f : 0.0f;
  Ta[tid] = make_float2(idv, 0.0f);
  Ot[tid] = make_float2(idv, 0.0f);
  __syncthreads();

  const int t_lo = (j >= 2) ? j - 2 : 0;
  float2* term = Ta; float2* nxt = Tb;
  for (int k = 1; k <= 12; k++) {
    float2 acc = make_float2(0.f, 0.f);
    if (act) {
      int t_hi = (j + 2 < c - 1) ? j + 2 : c - 1;
      for (int t = t_lo; t <= t_hi; t++) {
        float2 xv = term[i*CUT + t], yv = Bm[t*CUT + j];
        acc.x += xv.x*yv.x - xv.y*yv.y;
        acc.y += xv.x*yv.y + xv.y*yv.x;
      }
      float inv = 1.0f/(float)k;
      acc.x *= inv; acc.y *= inv;
      nxt[i*CUT + j] = acc;
      Ot[i*CUT + j].x += acc.x;
      Ot[i*CUT + j].y += acc.y;
    }
    float2* z = term; term = nxt; nxt = z;
    __syncthreads();
  }
  for (int q = 0; q < 8; q++) {   // 8 squarings (2^8 scaling)
    float2 acc = make_float2(0.f, 0.f);
    if (act) {
      for (int t = 0; t < c; t++) {
        float2 xv = Ot[i*CUT + t], yv = Ot[t*CUT + j];
        acc.x += xv.x*yv.x - xv.y*yv.y;
        acc.y += xv.x*yv.y + xv.y*yv.x;
      }
    }
    __syncthreads();
    if (act) Ot[i*CUT + j] = acc;
    __syncthreads();
  }

  if (task < 648) {
    if (act) {
      int off = (s < CUT) ? s*(s+1)*(2*s+1)/6
                          : SECT - ((27-s)*(28-s)*(55-2*s))/6;
      // TRANSPOSED store: [col u = j][cell row i]
      g_bs[gid][off + j*c + i] = Ot[tid];
    }
  } else {
    int u = task - 648;
    int circ = u / 12, rem = u % 12;
    int l = rem / 6, w = (rem / 3) % 2, m = rem % 3;
    int pi = (circ*2 + l)*3 + m;
    double phase;
    if (w == 0) phase = (double)vph1[pi] * (double)j;                        // M1 = S * R(vph1)
    else        phase = (double)vph2[pi] * (double)j + (double)kk[pi]*(double)(i*i); // M2 = K*D*R(vph2)
    float cr = (float)cos(phase), ci = (float)sin(phase);
    float2 sv = Ot[tid];
    g_sng[u][tid] = make_float2(sv.x*cr - sv.y*ci, sv.x*ci + sv.y*cr);
  }
}

// ============ initial displacement vectors: coherent-state closed form ============
__global__ void __launch_bounds__(256) dvec_kernel(const float* __restrict__ x)
{
  int tid = blockIdx.x*blockDim.x + threadIdx.x;
  if (tid >= 1024*6) return;
  int b = tid / 6, colx = tid % 6, circ = colx / 3, m = colx % 3;
  double xv = (double)x[tid];
  double c = exp(-0.5 * xv * xv);
  #pragma unroll
  for (int n = 0; n < CUT; n++) {
    g_dvec[circ][b][m][n] = (float)c;
    c *= xv * rsqrt((double)(n + 1));
  }
}

// ================= main evolution: one CTA per (batch, circuit) =================
__global__ void __launch_bounds__(NT, 4) evolve_kernel(float* __restrict__ out)
{
  __shared__ float2 spf[DIM];                 // state
  __shared__ alignas(16) float2 sg[SECT];     // staged gate
  __shared__ float  sd[3*CUT];
  __shared__ float  sred[3][NT/32];

  const int tid = threadIdx.x;
  const int b = blockIdx.x, circ = blockIdx.y;

  if (tid < 3*CUT) sd[tid] = g_dvec[circ][b][tid/CUT][tid%CUT];
  __syncthreads();
  for (int idx = tid; idx < DIM; idx += NT) {
    int i0 = idx / 196, j0 = (idx / CUT) % CUT, k0 = idx % CUT;
    spf[idx] = make_float2(sd[i0]*sd[CUT + j0]*sd[2*CUT + k0], 0.0f);
  }

  // ---- BS job decode: 392 jobs = (sector cell) x (fiber half of 7) ----
  int s = 0, csz = 1, pm = 0, gread = 0, row = 0, col = 0, r0 = 0;
  const bool bs_act = (tid < 392);
  if (bs_act) {
    int jj = tid, cum = 0, ss = 0;
    for (ss = 0; ss < 27; ss++) {
      int cc = (ss < CUT) ? ss + 1 : 27 - ss;
      if (jj < cum + 2*cc) break;
      cum += 2*cc;
    }
    s   = ss;
    csz = (s < CUT) ? s + 1 : 27 - s;
    pm  = (s < CUT) ? 0 : s - 13;
    int q = jj - cum;
    int half = q / csz;
    int idxs = q % csz;
    r0  = half * 7;
    row = pm + idxs; col = s - row;
    int off = (s < CUT) ? s*(s+1)*(2*s+1)/6 : SECT - ((27-s)*(28-s)*(55-2*s))/6;
    gread = off + idxs;            // transposed layout: addr = gread + u*csz
  }
  const int in01 = (pm*13 + s)*CUT;         // mode01 input base (u stride 182)
  const int ob01 = (row*CUT + col)*CUT;     // mode01 output base
  const int in12 = pm*13 + s;               // mode12 input base (u stride 13)
  const int ob12 = row*CUT + col;           // mode12 output cell (i stride 196)

  // ---- single-mode decode: 392 jobs = (output row a: warp-uniform) x (fiber group of 7) ----
  const int sm_a   = tid / 28;              // output row (0..13), uniform within 28-lane groups
  const int sm_grp = tid % 28;              // fiber group
  const bool sm_act = (tid < 392);
  __syncthreads();

  const int m1s[3] = {0, 1, 0};   // PAIRS = [(0,1),(1,2),(0,1)]
  for (int l = 0; l < 2; l++) {
    for (int half_ = 0; half_ < 2; half_++) {
      // ---- 3 beamsplitter gates ----
      for (int p = 0; p < 3; p++) {
        const float4* gm4 = (const float4*)g_bs[(circ*2 + l)*6 + half_*3 + p];
        float4* sg4 = (float4*)sg;
        for (int ii = tid; ii < SECT/2; ii += NT) sg4[ii] = gm4[ii];
        __syncthreads();
        float2 acc[7];
        if (bs_act) {
          #pragma unroll
          for (int r = 0; r < 7; r++) acc[r] = make_float2(0.f, 0.f);
          if (m1s[p] == 0) {          // contract axes (0,1); fiber axis 2 (stride 1)
            const float2* fbase = spf + in01 + r0;
            for (int u = 0; u < csz; u++) {
              float2 w = sg[gread + u*csz];
              const float2* f = fbase + u*182;
              #pragma unroll
              for (int r = 0; r < 7; r++) {
                float2 v = f[r];
                acc[r].x = fmaf(w.x, v.x, fmaf(-w.y, v.y, acc[r].x));
                acc[r].y = fmaf(w.x, v.y, fmaf( w.y, v.x, acc[r].y));
              }
            }
          } else {                    // contract axes (1,2); fiber axis 0 (stride 196)
            const float2* fbase = spf + in12 + r0*196;
            for (int u = 0; u < csz; u++) {
              float2 w = sg[gread + u*csz];
              const float2* f = fbase + u*13;
              #pragma unroll
              for (int r = 0; r < 7; r++) {
                float2 v = f[r*196];
                acc[r].x = fmaf(w.x, v.x, fmaf(-w.y, v.y, acc[r].x));
                acc[r].y = fmaf(w.x, v.y, fmaf( w.y, v.x, acc[r].y));
              }
            }
          }
        }
        __syncthreads();
        if (bs_act) {
          if (m1s[p] == 0) {
            float2* o = spf + ob01 + r0;
            #pragma unroll
            for (int r = 0; r < 7; r++) o[r] = acc[r];
          } else {
            #pragma unroll
            for (int r = 0; r < 7; r++) spf[(r0 + r)*196 + ob12] = acc[r];
          }
        }
        // no sync: next staging writes sg (disjoint from spf); barrier below covers both
      }
      // ---- 3 combined single-mode gates ----
      // half_==0: M1 = S*R -> checkerboard sparse (skip odd parity terms)
      for (int m = 0; m < 3; m++) {
        const float2* gm = g_sng[(circ*2 + l)*6 + half_*3 + m];
        if (tid < 196) sg[tid] = gm[tid];
        __syncthreads();
        float2 acc[7];
        int fbase = 0, tstep = 1, qstep = 1;
        if (sm_act) {
          if (m == 0)      { fbase = sm_grp*7;                               tstep = 196; qstep = 1;  }
          else if (m == 1) { fbase = (sm_grp >> 1)*196 + (sm_grp & 1)*7;     tstep = CUT; qstep = 1;  }
          else             { fbase = sm_grp*98;                              tstep = 1;   qstep = CUT; }
          #pragma unroll
          for (int q = 0; q < 7; q++) acc[q] = make_float2(0.f, 0.f);
          int t0 = (half_ == 0) ? (sm_a & 1) : 0;
          int dt = (half_ == 0) ? 2 : 1;
          for (int t = t0; t < CUT; t += dt) {
            float2 g = sg[sm_a*CUT + t];
            const float2* f = spf + fbase + t*tstep;
            #pragma unroll
            for (int q = 0; q < 7; q++) {
              float2 v = f[q*qstep];
              acc[q].x = fmaf(g.x, v.x, fmaf(-g.y, v.y, acc[q].x));
              acc[q].y = fmaf(g.x, v.y, fmaf( g.y, v.x, acc[q].y));
            }
          }
        }
        __syncthreads();
        if (sm_act) {
          float2* o = spf + fbase + sm_a*tstep;
          #pragma unroll
          for (int q = 0; q < 7; q++) o[q*qstep] = acc[q];
        }
        // no sync: next staging writes sg only
      }
    }
  }
  __syncthreads();

  // ---- expectations: single fused sweep for all 3 modes ----
  {
    float l0 = 0.f, l1 = 0.f, l2 = 0.f;
    for (int idx = tid; idx < DIM; idx += NT) {
      int i0 = idx / 196, rem = idx % 196;
      int j0 = rem / CUT, k0 = rem % CUT;
      float2 a2 = spf[idx];
      if (i0 < CUT-1) {
        float2 b2 = spf[idx + 196];
        l0 += sqrtf((float)(i0+1)) * (a2.x*b2.x + a2.y*b2.y);
      }
      if (j0 < CUT-1) {
        float2 b2 = spf[idx + CUT];
        l1 += sqrtf((float)(j0+1)) * (a2.x*b2.x + a2.y*b2.y);
      }
      if (k0 < CUT-1) {
        float2 b2 = spf[idx + 1];
        l2 += sqrtf((float)(k0+1)) * (a2.x*b2.x + a2.y*b2.y);
      }
    }
    #pragma unroll
    for (int o = 16; o > 0; o >>= 1) {
      l0 += __shfl_down_sync(0xffffffffu, l0, o);
      l1 += __shfl_down_sync(0xffffffffu, l1, o);
      l2 += __shfl_down_sync(0xffffffffu, l2, o);
    }
    if ((tid & 31) == 0) {
      sred[0][tid >> 5] = l0;
      sred[1][tid >> 5] = l1;
      sred[2][tid >> 5] = l2;
    }
    __syncthreads();
    if (tid < 3) {
      float tot = 0.f;
      #pragma unroll
      for (int w2 = 0; w2 < NT/32; w2++) tot += sred[tid][w2];
      out[b*6 + circ*3 + tid] = 2.f * tot;
    }
  }
}

// ================================ launch ================================
extern "C" void kernel_launch(void* const* d_in, const int* in_sizes, int n_in,
                              void* d_out, int out_size)
{
  (void)in_sizes; (void)n_in; (void)out_size;
  const float* x    = (const float*)d_in[0];
  const float* th1  = (const float*)d_in[1];
  const float* ph1  = (const float*)d_in[2];
  const float* vph1 = (const float*)d_in[3];
  const float* rr   = (const float*)d_in[4];
  const float* phr  = (const float*)d_in[5];
  const float* th2  = (const float*)d_in[6];
  const float* ph2  = (const float*)d_in[7];
  const float* vph2 = (const float*)d_in[8];
  const float* aa   = (const float*)d_in[9];
  const float* pha  = (const float*)d_in[10];
  const float* kk   = (const float*)d_in[11];

  gates_kernel<<<672, 196>>>(th1, ph1, vph1, rr, phr, th2, ph2, vph2, aa, pha, kk);
  dvec_kernel<<<24, 256>>>(x);
  dim3 grid(1024, 2);
  evolve_kernel<<<grid, NT>>>((float*)d_out);
}

// round 8
// speedup vs baseline: 1.8771x; 1.8771x over previous
#include <cuda_runtime.h>

#define CUT  14
#define DIM  2744          // 14^3
#define SECT 1834          // sum over sectors of c(s)^2
#define NT   448           // evolve threads per CTA

// ---------------- persistent device scratch (no allocs allowed) ----------------
__device__ float2 g_bs[24][SECT];        // 24 beamsplitter gates, sector-packed [row i][col u]
__device__ float2 g_sng[24][CUT*CUT];    // 24 combined single-mode gates
__device__ float  g_dvec[2][1024][3][CUT]; // initial displacement vectors (real)

// ================= gate precompute: fp32 expm (s=8, terms=12, banded Taylor) =================
__global__ void __launch_bounds__(196) gates_kernel(
    const float* __restrict__ th1, const float* __restrict__ ph1,
    const float* __restrict__ vph1, const float* __restrict__ rr,
    const float* __restrict__ phr, const float* __restrict__ th2,
    const float* __restrict__ ph2, const float* __restrict__ vph2,
    const float* __restrict__ aa, const float* __restrict__ pha,
    const float* __restrict__ kk)
{
  __shared__ float2 Bm[196], Ta[196], Tb[196], Ot[196];
  const int tid = threadIdx.x;
  const int i = tid / CUT, j = tid % CUT;
  const int task = blockIdx.x;

  int c = CUT, s = 0, pm = 0, gid = -1;
  double2 h = make_double2(0.0, 0.0);

  if (task < 648) {
    gid = task / 27; s = task % 27;
    pm = (s < CUT) ? 0 : s - (CUT-1);
    c  = (s < CUT) ? s + 1 : 2*CUT - 1 - s;
    int circ = gid / 12, rem = gid % 12;
    int l = rem / 6, w = (rem / 3) % 2, p = rem % 3;
    int pi = (circ*2 + l)*3 + p;
    double th = (double)((w ? th2 : th1)[pi]);
    double ph = (double)((w ? ph2 : ph1)[pi]);
    if (i < c && j < c) {
      int P = pm + i, Q = s - P;
      if (j == i - 1) {            // theta*e^{i phi} * sqrt(P*(Q+1))
        double mag = th * sqrt((double)P * (double)(Q + 1));
        h.x = mag * cos(ph); h.y = mag * sin(ph);
      } else if (j == i + 1) {     // -theta*e^{-i phi} * sqrt((P+1)*Q)
        double mag = th * sqrt((double)(P + 1) * (double)Q);
        h.x = -mag * cos(ph); h.y = mag * sin(ph);
      }
    }
  } else {
    int u = task - 648;
    int circ = u / 12, rem = u % 12;
    int l = rem / 6, w = (rem / 3) % 2, m = rem % 3;
    int pi = (circ*2 + l)*3 + m;
    if (w == 0) {  // squeeze
      double rv = (double)rr[pi], pv = (double)phr[pi];
      double zr = rv*cos(pv), zi = rv*sin(pv);
      if (j == i + 2) {
        double mag = 0.5*sqrt((double)(i+1)*(double)(i+2));
        h.x = mag*zr; h.y = -mag*zi;
      } else if (i == j + 2) {
        double mag = 0.5*sqrt((double)(j+1)*(double)(j+2));
        h.x = -mag*zr; h.y = -mag*zi;
      }
    } else {       // disp
      double av = (double)aa[pi], pv = (double)pha[pi];
      double ar = av*cos(pv), ai = av*sin(pv);
      if (i == j + 1) {
        double mag = sqrt((double)(j+1));
        h.x = mag*ar; h.y = mag*ai;
      } else if (j == i + 1) {
        double mag = sqrt((double)(i+1));
        h.x = -mag*ar; h.y = mag*ai;
      }
    }
  }

  const bool act = (i < c && j < c);
  const double sc = 1.0/256.0;   // 2^-8
  Bm[tid] = make_float2((float)(h.x*sc), (float)(h.y*sc));
  float idv = (act && i == j) ? 1.0f : 0.0f;
  Ta[tid] = make_float2(idv, 0.0f);
  Ot[tid] = make_float2(idv, 0.0f);
  __syncthreads();

  const int t_lo = (j >= 2) ? j - 2 : 0;
  float2* term = Ta; float2* nxt = Tb;
  for (int k = 1; k <= 12; k++) {
    float2 acc = make_float2(0.f, 0.f);
    if (act) {
      int t_hi = (j + 2 < c - 1) ? j + 2 : c - 1;
      for (int t = t_lo; t <= t_hi; t++) {
        float2 xv = term[i*CUT + t], yv = Bm[t*CUT + j];
        acc.x += xv.x*yv.x - xv.y*yv.y;
        acc.y += xv.x*yv.y + xv.y*yv.x;
      }
      float inv = 1.0f/(float)k;
      acc.x *= inv; acc.y *= inv;
      nxt[i*CUT + j] = acc;
      Ot[i*CUT + j].x += acc.x;
      Ot[i*CUT + j].y += acc.y;
    }
    float2* z = term; term = nxt; nxt = z;
    __syncthreads();
  }
  for (int q = 0; q < 8; q++) {   // 8 squarings (2^8 scaling)
    float2 acc = make_float2(0.f, 0.f);
    if (act) {
      for (int t = 0; t < c; t++) {
        float2 xv = Ot[i*CUT + t], yv = Ot[t*CUT + j];
        acc.x += xv.x*yv.x - xv.y*yv.y;
        acc.y += xv.x*yv.y + xv.y*yv.x;
      }
    }
    __syncthreads();
    if (act) Ot[i*CUT + j] = acc;
    __syncthreads();
  }

  if (task < 648) {
    if (act) {
      int off = (s < CUT) ? s*(s+1)*(2*s+1)/6
                          : SECT - ((27-s)*(28-s)*(55-2*s))/6;
      g_bs[gid][off + i*c + j] = Ot[tid];   // row-major (R2 layout)
    }
  } else {
    int u = task - 648;
    int circ = u / 12, rem = u % 12;
    int l = rem / 6, w = (rem / 3) % 2, m = rem % 3;
    int pi = (circ*2 + l)*3 + m;
    double phase;
    if (w == 0) phase = (double)vph1[pi] * (double)j;                        // M1 = S * R(vph1)
    else        phase = (double)vph2[pi] * (double)j + (double)kk[pi]*(double)(i*i); // M2 = K*D*R(vph2)
    float cr = (float)cos(phase), ci = (float)sin(phase);
    float2 sv = Ot[tid];
    g_sng[u][tid] = make_float2(sv.x*cr - sv.y*ci, sv.x*ci + sv.y*cr);
  }
}

// ============ initial displacement vectors: coherent-state closed form ============
__global__ void __launch_bounds__(256) dvec_kernel(const float* __restrict__ x)
{
  int tid = blockIdx.x*blockDim.x + threadIdx.x;
  if (tid >= 1024*6) return;
  int b = tid / 6, colx = tid % 6, circ = colx / 3, m = colx % 3;
  double xv = (double)x[tid];
  double c = exp(-0.5 * xv * xv);
  #pragma unroll
  for (int n = 0; n < CUT; n++) {
    g_dvec[circ][b][m][n] = (float)c;
    c *= xv * rsqrt((double)(n + 1));
  }
}

// ================= main evolution: one CTA per (batch, circuit) — R2 structure =================
__device__ __forceinline__ void cmac(float2& acc, float2 w, float2 v) {
  acc.x = fmaf(w.x, v.x, fmaf(-w.y, v.y, acc.x));
  acc.y = fmaf(w.x, v.y, fmaf( w.y, v.x, acc.y));
}

__global__ void __launch_bounds__(NT, 4) evolve_kernel(float* __restrict__ out)
{
  __shared__ float2 sp[DIM];
  __shared__ float2 sg[SECT];
  __shared__ float  sd[3*CUT];
  __shared__ float  sred[3][NT/32];

  const int tid = threadIdx.x;
  const int b = blockIdx.x, circ = blockIdx.y;

  if (tid < 3*CUT) sd[tid] = g_dvec[circ][b][tid/CUT][tid%CUT];
  __syncthreads();
  for (int idx = tid; idx < DIM; idx += NT) {
    int i0 = idx / 196, j0 = (idx / CUT) % CUT, k0 = idx % CUT;
    sp[idx] = make_float2(sd[i0]*sd[CUT + j0]*sd[2*CUT + k0], 0.0f);
  }

  // ---- BS job decode: 392 jobs = (sector cell) x (fiber half of 7) ----
  int s = 0, csz = 1, pm = 0, gbase = 0, row = 0, col = 0, r0 = 0;
  const bool bs_act = (tid < 392);
  if (bs_act) {
    int jj = tid, cum = 0, ss = 0;
    for (ss = 0; ss < 27; ss++) {
      int cc = (ss < CUT) ? ss + 1 : 27 - ss;
      if (jj < cum + 2*cc) break;
      cum += 2*cc;
    }
    s   = ss;
    csz = (s < CUT) ? s + 1 : 27 - s;
    pm  = (s < CUT) ? 0 : s - 13;
    int q = jj - cum;
    int half = q / csz;
    int idxs = q % csz;
    r0  = half * 7;
    row = pm + idxs; col = s - row;
    int off = (s < CUT) ? s*(s+1)*(2*s+1)/6 : SECT - ((27-s)*(28-s)*(55-2*s))/6;
    gbase = off + idxs*csz;
  }
  const int in01 = (pm*13 + s)*CUT;         // mode01 input base (u stride 182)
  const int ob01 = (row*CUT + col)*CUT;     // mode01 output base
  const int in12 = pm*13 + s;               // mode12 input base (u stride 13)
  const int ob12 = row*CUT + col;           // mode12 output cell (i stride 196)
  __syncthreads();

  const int m1s[3] = {0, 1, 0};   // PAIRS = [(0,1),(1,2),(0,1)]
  for (int l = 0; l < 2; l++) {
    for (int half_ = 0; half_ < 2; half_++) {
      // ---- 3 beamsplitter gates ----
      for (int p = 0; p < 3; p++) {
        const float2* gm = g_bs[(circ*2 + l)*6 + half_*3 + p];
        for (int ii = tid; ii < SECT; ii += NT) sg[ii] = gm[ii];
        __syncthreads();
        float2 acc[7];
        if (bs_act) {
          #pragma unroll
          for (int r = 0; r < 7; r++) acc[r] = make_float2(0.f, 0.f);
          if (m1s[p] == 0) {          // contract axes (0,1); fiber axis 2 (stride 1)
            for (int u = 0; u < csz; u++) {
              float2 w = sg[gbase + u];
              const float2* f = sp + in01 + u*182 + r0;
              #pragma unroll
              for (int r = 0; r < 7; r++) cmac(acc[r], w, f[r]);
            }
          } else {                    // contract axes (1,2); fiber axis 0 (stride 196)
            for (int u = 0; u < csz; u++) {
              float2 w = sg[gbase + u];
              const float2* f = sp + in12 + u*13 + r0*196;
              #pragma unroll
              for (int r = 0; r < 7; r++) cmac(acc[r], w, f[r*196]);
            }
          }
        }
        __syncthreads();
        if (bs_act) {
          if (m1s[p] == 0) {
            float2* o = sp + ob01 + r0;
            #pragma unroll
            for (int r = 0; r < 7; r++) o[r] = acc[r];
          } else {
            #pragma unroll
            for (int r = 0; r < 7; r++) sp[(r0 + r)*196 + ob12] = acc[r];
          }
        }
        __syncthreads();
      }
      // ---- 3 combined single-mode gates: 392 jobs = (fiber) x (output half) ----
      for (int m = 0; m < 3; m++) {
        const float2* gm = g_sng[(circ*2 + l)*6 + half_*3 + m];
        if (tid < 196) sg[tid] = gm[tid];
        __syncthreads();
        float2 o[7];
        int base = 0, stride = 1, h7 = 0;
        if (tid < 392) {
          int f = tid >> 1;
          h7 = (tid & 1) * 7;
          if (m == 0)      { base = f;                         stride = 196; }
          else if (m == 1) { base = (f/CUT)*196 + (f%CUT);     stride = CUT; }
          else             { base = f*CUT;                     stride = 1;   }
          float2 fb[CUT];
          #pragma unroll
          for (int t = 0; t < CUT; t++) fb[t] = sp[base + t*stride];
          #pragma unroll
          for (int a = 0; a < 7; a++) {
            float2 acc2 = make_float2(0.f, 0.f);
            #pragma unroll
            for (int t = 0; t < CUT; t++) cmac(acc2, sg[(h7 + a)*CUT + t], fb[t]);
            o[a] = acc2;
          }
        }
        __syncthreads();
        if (tid < 392) {
          #pragma unroll
          for (int a = 0; a < 7; a++) sp[base + (h7 + a)*stride] = o[a];
        }
        __syncthreads();
      }
    }
  }

  // ---- expectations: single fused sweep for all 3 modes ----
  {
    float l0 = 0.f, l1 = 0.f, l2 = 0.f;
    for (int idx = tid; idx < DIM; idx += NT) {
      int i0 = idx / 196, rem = idx % 196;
      int j0 = rem / CUT, k0 = rem % CUT;
      float2 a2 = sp[idx];
      if (i0 < CUT-1) {
        float2 b2 = sp[idx + 196];
        l0 += sqrtf((float)(i0+1)) * (a2.x*b2.x + a2.y*b2.y);
      }
      if (j0 < CUT-1) {
        float2 b2 = sp[idx + CUT];
        l1 += sqrtf((float)(j0+1)) * (a2.x*b2.x + a2.y*b2.y);
      }
      if (k0 < CUT-1) {
        float2 b2 = sp[idx + 1];
        l2 += sqrtf((float)(k0+1)) * (a2.x*b2.x + a2.y*b2.y);
      }
    }
    #pragma unroll
    for (int o = 16; o > 0; o >>= 1) {
      l0 += __shfl_down_sync(0xffffffffu, l0, o);
      l1 += __shfl_down_sync(0xffffffffu, l1, o);
      l2 += __shfl_down_sync(0xffffffffu, l2, o);
    }
    if ((tid & 31) == 0) {
      sred[0][tid >> 5] = l0;
      sred[1][tid >> 5] = l1;
      sred[2][tid >> 5] = l2;
    }
    __syncthreads();
    if (tid < 3) {
      float tot = 0.f;
      #pragma unroll
      for (int w2 = 0; w2 < NT/32; w2++) tot += sred[tid][w2];
      out[b*6 + circ*3 + tid] = 2.f * tot;
    }
  }
}

// ================================ launch ================================
extern "C" void kernel_launch(void* const* d_in, const int* in_sizes, int n_in,
                              void* d_out, int out_size)
{
  (void)in_sizes; (void)n_in; (void)out_size;
  const float* x    = (const float*)d_in[0];
  const float* th1  = (const float*)d_in[1];
  const float* ph1  = (const float*)d_in[2];
  const float* vph1 = (const float*)d_in[3];
  const float* rr   = (const float*)d_in[4];
  const float* phr  = (const float*)d_in[5];
  const float* th2  = (const float*)d_in[6];
  const float* ph2  = (const float*)d_in[7];
  const float* vph2 = (const float*)d_in[8];
  const float* aa   = (const float*)d_in[9];
  const float* pha  = (const float*)d_in[10];
  const float* kk   = (const float*)d_in[11];

  gates_kernel<<<672, 196>>>(th1, ph1, vph1, rr, phr, th2, ph2, vph2, aa, pha, kk);
  dvec_kernel<<<24, 256>>>(x);
  dim3 grid(1024, 2);
  evolve_kernel<<<grid, NT>>>((float*)d_out);
}

// round 9
// speedup vs baseline: 1.8776x; 1.0003x over previous
#include <cuda_runtime.h>

#define CUT  14
#define DIM  2744          // 14^3
#define SECT 1834          // sum over sectors of c(s)^2
#define NT   448           // evolve threads per CTA

// ---------------- persistent device scratch (no allocs allowed) ----------------
__device__ float2 g_bs[24][SECT];        // 24 beamsplitter gates, sector-packed [row i][col u]
__device__ float2 g_sng[24][CUT*CUT];    // 24 combined single-mode gates
__device__ float  g_dvec[2][1024][3][CUT]; // initial displacement vectors (real)

// ================= gate precompute: fp32 expm (s=8, terms=12, banded Taylor) =================
__global__ void __launch_bounds__(196) gates_kernel(
    const float* __restrict__ th1, const float* __restrict__ ph1,
    const float* __restrict__ vph1, const float* __restrict__ rr,
    const float* __restrict__ phr, const float* __restrict__ th2,
    const float* __restrict__ ph2, const float* __restrict__ vph2,
    const float* __restrict__ aa, const float* __restrict__ pha,
    const float* __restrict__ kk)
{
  __shared__ float2 Bm[196], Ta[196], Tb[196], Ot[196];
  const int tid = threadIdx.x;
  const int i = tid / CUT, j = tid % CUT;
  const int task = blockIdx.x;

  int c = CUT, s = 0, pm = 0, gid = -1;
  double2 h = make_double2(0.0, 0.0);

  if (task < 648) {
    gid = task / 27; s = task % 27;
    pm = (s < CUT) ? 0 : s - (CUT-1);
    c  = (s < CUT) ? s + 1 : 2*CUT - 1 - s;
    int circ = gid / 12, rem = gid % 12;
    int l = rem / 6, w = (rem / 3) % 2, p = rem % 3;
    int pi = (circ*2 + l)*3 + p;
    double th = (double)((w ? th2 : th1)[pi]);
    double ph = (double)((w ? ph2 : ph1)[pi]);
    if (i < c && j < c) {
      int P = pm + i, Q = s - P;
      if (j == i - 1) {            // theta*e^{i phi} * sqrt(P*(Q+1))
        double mag = th * sqrt((double)P * (double)(Q + 1));
        h.x = mag * cos(ph); h.y = mag * sin(ph);
      } else if (j == i + 1) {     // -theta*e^{-i phi} * sqrt((P+1)*Q)
        double mag = th * sqrt((double)(P + 1) * (double)Q);
        h.x = -mag * cos(ph); h.y = mag * sin(ph);
      }
    }
  } else {
    int u = task - 648;
    int circ = u / 12, rem = u % 12;
    int l = rem / 6, w = (rem / 3) % 2, m = rem % 3;
    int pi = (circ*2 + l)*3 + m;
    if (w == 0) {  // squeeze
      double rv = (double)rr[pi], pv = (double)phr[pi];
      double zr = rv*cos(pv), zi = rv*sin(pv);
      if (j == i + 2) {
        double mag = 0.5*sqrt((double)(i+1)*(double)(i+2));
        h.x = mag*zr; h.y = -mag*zi;
      } else if (i == j + 2) {
        double mag = 0.5*sqrt((double)(j+1)*(double)(j+2));
        h.x = -mag*zr; h.y = -mag*zi;
      }
    } else {       // disp
      double av = (double)aa[pi], pv = (double)pha[pi];
      double ar = av*cos(pv), ai = av*sin(pv);
      if (i == j + 1) {
        double mag = sqrt((double)(j+1));
        h.x = mag*ar; h.y = mag*ai;
      } else if (j == i + 1) {
        double mag = sqrt((double)(i+1));
        h.x = -mag*ar; h.y = mag*ai;
      }
    }
  }

  const bool act = (i < c && j < c);
  const double sc = 1.0/256.0;   // 2^-8
  Bm[tid] = make_float2((float)(h.x*sc), (float)(h.y*sc));
  float idv = (act && i == j) ? 1.0f : 0.0f;
  Ta[tid] = make_float2(idv, 0.0f);
  Ot[tid] = make_float2(idv, 0.0f);
  __syncthreads();

  const int t_lo = (j >= 2) ? j - 2 : 0;
  float2* term = Ta; float2* nxt = Tb;
  for (int k = 1; k <= 12; k++) {
    float2 acc = make_float2(0.f, 0.f);
    if (act) {
      int t_hi = (j + 2 < c - 1) ? j + 2 : c - 1;
      for (int t = t_lo; t <= t_hi; t++) {
        float2 xv = term[i*CUT + t], yv = Bm[t*CUT + j];
        acc.x += xv.x*yv.x - xv.y*yv.y;
        acc.y += xv.x*yv.y + xv.y*yv.x;
      }
      float inv = 1.0f/(float)k;
      acc.x *= inv; acc.y *= inv;
      nxt[i*CUT + j] = acc;
      Ot[i*CUT + j].x += acc.x;
      Ot[i*CUT + j].y += acc.y;
    }
    float2* z = term; term = nxt; nxt = z;
    __syncthreads();
  }
  for (int q = 0; q < 8; q++) {   // 8 squarings (2^8 scaling)
    float2 acc = make_float2(0.f, 0.f);
    if (act) {
      for (int t = 0; t < c; t++) {
        float2 xv = Ot[i*CUT + t], yv = Ot[t*CUT + j];
        acc.x += xv.x*yv.x - xv.y*yv.y;
        acc.y += xv.x*yv.y + xv.y*yv.x;
      }
    }
    __syncthreads();
    if (act) Ot[i*CUT + j] = acc;
    __syncthreads();
  }

  if (task < 648) {
    if (act) {
      int off = (s < CUT) ? s*(s+1)*(2*s+1)/6
                          : SECT - ((27-s)*(28-s)*(55-2*s))/6;
      g_bs[gid][off + i*c + j] = Ot[tid];   // row-major (R2 layout)
    }
  } else {
    int u = task - 648;
    int circ = u / 12, rem = u % 12;
    int l = rem / 6, w = (rem / 3) % 2, m = rem % 3;
    int pi = (circ*2 + l)*3 + m;
    double phase;
    if (w == 0) phase = (double)vph1[pi] * (double)j;                        // M1 = S * R(vph1)
    else        phase = (double)vph2[pi] * (double)j + (double)kk[pi]*(double)(i*i); // M2 = K*D*R(vph2)
    float cr = (float)cos(phase), ci = (float)sin(phase);
    float2 sv = Ot[tid];
    g_sng[u][tid] = make_float2(sv.x*cr - sv.y*ci, sv.x*ci + sv.y*cr);
  }
}

// ============ initial displacement vectors: coherent-state closed form ============
__global__ void __launch_bounds__(256) dvec_kernel(const float* __restrict__ x)
{
  int tid = blockIdx.x*blockDim.x + threadIdx.x;
  if (tid >= 1024*6) return;
  int b = tid / 6, colx = tid % 6, circ = colx / 3, m = colx % 3;
  double xv = (double)x[tid];
  double c = exp(-0.5 * xv * xv);
  #pragma unroll
  for (int n = 0; n < CUT; n++) {
    g_dvec[circ][b][m][n] = (float)c;
    c *= xv * rsqrt((double)(n + 1));
  }
}

// ================= main evolution: one CTA per (batch, circuit) — 2-sync/gate =================
__device__ __forceinline__ void cmac(float2& acc, float2 w, float2 v) {
  acc.x = fmaf(w.x, v.x, fmaf(-w.y, v.y, acc.x));
  acc.y = fmaf(w.x, v.y, fmaf( w.y, v.x, acc.y));
}

__global__ void __launch_bounds__(NT, 4) evolve_kernel(float* __restrict__ out)
{
  __shared__ float2 sp[DIM];
  __shared__ float2 sg[SECT];
  __shared__ float  sd[3*CUT];
  __shared__ float  sred[3][NT/32];

  const int tid = threadIdx.x;
  const int b = blockIdx.x, circ = blockIdx.y;

  if (tid < 3*CUT) sd[tid] = g_dvec[circ][b][tid/CUT][tid%CUT];
  __syncthreads();
  for (int idx = tid; idx < DIM; idx += NT) {
    int i0 = idx / 196, j0 = (idx / CUT) % CUT, k0 = idx % CUT;
    sp[idx] = make_float2(sd[i0]*sd[CUT + j0]*sd[2*CUT + k0], 0.0f);
  }

  // ---- BS job decode: 392 jobs = (sector cell) x (fiber half of 7) ----
  int s = 0, csz = 1, pm = 0, gbase = 0, row = 0, col = 0, r0 = 0;
  const bool bs_act = (tid < 392);
  if (bs_act) {
    int jj = tid, cum = 0, ss = 0;
    for (ss = 0; ss < 27; ss++) {
      int cc = (ss < CUT) ? ss + 1 : 27 - ss;
      if (jj < cum + 2*cc) break;
      cum += 2*cc;
    }
    s   = ss;
    csz = (s < CUT) ? s + 1 : 27 - s;
    pm  = (s < CUT) ? 0 : s - 13;
    int q = jj - cum;
    int half = q / csz;
    int idxs = q % csz;
    r0  = half * 7;
    row = pm + idxs; col = s - row;
    int off = (s < CUT) ? s*(s+1)*(2*s+1)/6 : SECT - ((27-s)*(28-s)*(55-2*s))/6;
    gbase = off + idxs*csz;
  }
  const int in01 = (pm*13 + s)*CUT;         // mode01 input base (u stride 182)
  const int ob01 = (row*CUT + col)*CUT;     // mode01 output base
  const int in12 = pm*13 + s;               // mode12 input base (u stride 13)
  const int ob12 = row*CUT + col;           // mode12 output cell (i stride 196)
  // NOTE: no sync needed here; the staging of the first gate below writes sg
  // only, and the pre-compute barrier orders everything.

  const int m1s[3] = {0, 1, 0};   // PAIRS = [(0,1),(1,2),(0,1)]
  for (int l = 0; l < 2; l++) {
    for (int half_ = 0; half_ < 2; half_++) {
      // ---- 3 beamsplitter gates: [stage] sync [compute] sync [writeback]... ----
      for (int p = 0; p < 3; p++) {
        const float2* gm = g_bs[(circ*2 + l)*6 + half_*3 + p];
        for (int ii = tid; ii < SECT; ii += NT) sg[ii] = gm[ii];
        __syncthreads();
        float2 acc[7];
        if (bs_act) {
          #pragma unroll
          for (int r = 0; r < 7; r++) acc[r] = make_float2(0.f, 0.f);
          if (m1s[p] == 0) {          // contract axes (0,1); fiber axis 2 (stride 1)
            for (int u = 0; u < csz; u++) {
              float2 w = sg[gbase + u];
              const float2* f = sp + in01 + u*182 + r0;
              #pragma unroll
              for (int r = 0; r < 7; r++) cmac(acc[r], w, f[r]);
            }
          } else {                    // contract axes (1,2); fiber axis 0 (stride 196)
            for (int u = 0; u < csz; u++) {
              float2 w = sg[gbase + u];
              const float2* f = sp + in12 + u*13 + r0*196;
              #pragma unroll
              for (int r = 0; r < 7; r++) cmac(acc[r], w, f[r*196]);
            }
          }
        }
        __syncthreads();
        if (bs_act) {
          if (m1s[p] == 0) {
            float2* o = sp + ob01 + r0;
            #pragma unroll
            for (int r = 0; r < 7; r++) o[r] = acc[r];
          } else {
            #pragma unroll
            for (int r = 0; r < 7; r++) sp[(r0 + r)*196 + ob12] = acc[r];
          }
        }
        // no trailing sync: next staging writes sg (disjoint from sp);
        // the pre-compute barrier of the next gate orders both.
      }
      // ---- 3 combined single-mode gates: 392 jobs = (fiber) x (output half) ----
      for (int m = 0; m < 3; m++) {
        const float2* gm = g_sng[(circ*2 + l)*6 + half_*3 + m];
        if (tid < 196) sg[tid] = gm[tid];
        __syncthreads();
        float2 o[7];
        int base = 0, stride = 1, h7 = 0;
        if (tid < 392) {
          int f = tid >> 1;
          h7 = (tid & 1) * 7;
          if (m == 0)      { base = f;                         stride = 196; }
          else if (m == 1) { base = (f/CUT)*196 + (f%CUT);     stride = CUT; }
          else             { base = f*CUT;                     stride = 1;   }
          float2 fb[CUT];
          #pragma unroll
          for (int t = 0; t < CUT; t++) fb[t] = sp[base + t*stride];
          #pragma unroll
          for (int a = 0; a < 7; a++) {
            float2 acc2 = make_float2(0.f, 0.f);
            #pragma unroll
            for (int t = 0; t < CUT; t++) cmac(acc2, sg[(h7 + a)*CUT + t], fb[t]);
            o[a] = acc2;
          }
        }
        __syncthreads();
        if (tid < 392) {
          #pragma unroll
          for (int a = 0; a < 7; a++) sp[base + (h7 + a)*stride] = o[a];
        }
        // no trailing sync (same argument as above)
      }
    }
  }
  __syncthreads();   // order final writeback before the expectation sweep

  // ---- expectations: single fused sweep for all 3 modes ----
  {
    float l0 = 0.f, l1 = 0.f, l2 = 0.f;
    for (int idx = tid; idx < DIM; idx += NT) {
      int i0 = idx / 196, rem = idx % 196;
      int j0 = rem / CUT, k0 = rem % CUT;
      float2 a2 = sp[idx];
      if (i0 < CUT-1) {
        float2 b2 = sp[idx + 196];
        l0 += sqrtf((float)(i0+1)) * (a2.x*b2.x + a2.y*b2.y);
      }
      if (j0 < CUT-1) {
        float2 b2 = sp[idx + CUT];
        l1 += sqrtf((float)(j0+1)) * (a2.x*b2.x + a2.y*b2.y);
      }
      if (k0 < CUT-1) {
        float2 b2 = sp[idx + 1];
        l2 += sqrtf((float)(k0+1)) * (a2.x*b2.x + a2.y*b2.y);
      }
    }
    #pragma unroll
    for (int o = 16; o > 0; o >>= 1) {
      l0 += __shfl_down_sync(0xffffffffu, l0, o);
      l1 += __shfl_down_sync(0xffffffffu, l1, o);
      l2 += __shfl_down_sync(0xffffffffu, l2, o);
    }
    if ((tid & 31) == 0) {
      sred[0][tid >> 5] = l0;
      sred[1][tid >> 5] = l1;
      sred[2][tid >> 5] = l2;
    }
    __syncthreads();
    if (tid < 3) {
      float tot = 0.f;
      #pragma unroll
      for (int w2 = 0; w2 < NT/32; w2++) tot += sred[tid][w2];
      out[b*6 + circ*3 + tid] = 2.f * tot;
    }
  }
}

// ================================ launch ================================
extern "C" void kernel_launch(void* const* d_in, const int* in_sizes, int n_in,
                              void* d_out, int out_size)
{
  (void)in_sizes; (void)n_in; (void)out_size;
  const float* x    = (const float*)d_in[0];
  const float* th1  = (const float*)d_in[1];
  const float* ph1  = (const float*)d_in[2];
  const float* vph1 = (const float*)d_in[3];
  const float* rr   = (const float*)d_in[4];
  const float* phr  = (const float*)d_in[5];
  const float* th2  = (const float*)d_in[6];
  const float* ph2  = (const float*)d_in[7];
  const float* vph2 = (const float*)d_in[8];
  const float* aa   = (const float*)d_in[9];
  const float* pha  = (const float*)d_in[10];
  const float* kk   = (const float*)d_in[11];

  gates_kernel<<<672, 196>>>(th1, ph1, vph1, rr, phr, th2, ph2, vph2, aa, pha, kk);
  dvec_kernel<<<24, 256>>>(x);
  dim3 grid(1024, 2);
  evolve_kernel<<<grid, NT>>>((float*)d_out);
}

// round 10
// speedup vs baseline: 2.1295x; 1.1341x over previous
#include <cuda_runtime.h>

#define CUT  14
#define DIM  2744          // 14^3
#define SECT 1834          // sum over sectors of c(s)^2
#define NT   448           // evolve threads per CTA

// ---------------- persistent device scratch (no allocs allowed) ----------------
__device__ float2 g_bs[24][SECT];        // 24 beamsplitter gates, sector-packed [row i][col u]
__device__ float2 g_sng[24][CUT*CUT];    // 24 combined single-mode gates
__device__ float  g_dvec[2][1024][3][CUT]; // initial displacement vectors (real)

// ================= gate precompute: fp32 expm (s=8, terms=12, banded Taylor) =================
__global__ void __launch_bounds__(196) gates_kernel(
    const float* __restrict__ th1, const float* __restrict__ ph1,
    const float* __restrict__ vph1, const float* __restrict__ rr,
    const float* __restrict__ phr, const float* __restrict__ th2,
    const float* __restrict__ ph2, const float* __restrict__ vph2,
    const float* __restrict__ aa, const float* __restrict__ pha,
    const float* __restrict__ kk)
{
  __shared__ float2 Bm[196], Ta[196], Tb[196], Ot[196];
  const int tid = threadIdx.x;
  const int i = tid / CUT, j = tid % CUT;
  const int task = blockIdx.x;

  int c = CUT, s = 0, pm = 0, gid = -1;
  double2 h = make_double2(0.0, 0.0);

  if (task < 648) {
    gid = task / 27; s = task % 27;
    pm = (s < CUT) ? 0 : s - (CUT-1);
    c  = (s < CUT) ? s + 1 : 2*CUT - 1 - s;
    int circ = gid / 12, rem = gid % 12;
    int l = rem / 6, w = (rem / 3) % 2, p = rem % 3;
    int pi = (circ*2 + l)*3 + p;
    double th = (double)((w ? th2 : th1)[pi]);
    double ph = (double)((w ? ph2 : ph1)[pi]);
    if (i < c && j < c) {
      int P = pm + i, Q = s - P;
      if (j == i - 1) {            // theta*e^{i phi} * sqrt(P*(Q+1))
        double mag = th * sqrt((double)P * (double)(Q + 1));
        h.x = mag * cos(ph); h.y = mag * sin(ph);
      } else if (j == i + 1) {     // -theta*e^{-i phi} * sqrt((P+1)*Q)
        double mag = th * sqrt((double)(P + 1) * (double)Q);
        h.x = -mag * cos(ph); h.y = mag * sin(ph);
      }
    }
  } else {
    int u = task - 648;
    int circ = u / 12, rem = u % 12;
    int l = rem / 6, w = (rem / 3) % 2, m = rem % 3;
    int pi = (circ*2 + l)*3 + m;
    if (w == 0) {  // squeeze
      double rv = (double)rr[pi], pv = (double)phr[pi];
      double zr = rv*cos(pv), zi = rv*sin(pv);
      if (j == i + 2) {
        double mag = 0.5*sqrt((double)(i+1)*(double)(i+2));
        h.x = mag*zr; h.y = -mag*zi;
      } else if (i == j + 2) {
        double mag = 0.5*sqrt((double)(j+1)*(double)(j+2));
        h.x = -mag*zr; h.y = -mag*zi;
      }
    } else {       // disp
      double av = (double)aa[pi], pv = (double)pha[pi];
      double ar = av*cos(pv), ai = av*sin(pv);
      if (i == j + 1) {
        double mag = sqrt((double)(j+1));
        h.x = mag*ar; h.y = mag*ai;
      } else if (j == i + 1) {
        double mag = sqrt((double)(i+1));
        h.x = -mag*ar; h.y = mag*ai;
      }
    }
  }

  const bool act = (i < c && j < c);
  const double sc = 1.0/256.0;   // 2^-8
  Bm[tid] = make_float2((float)(h.x*sc), (float)(h.y*sc));
  float idv = (act && i == j) ? 1.0f : 0.0f;
  Ta[tid] = make_float2(idv, 0.0f);
  Ot[tid] = make_float2(idv, 0.0f);
  __syncthreads();

  const int t_lo = (j >= 2) ? j - 2 : 0;
  float2* term = Ta; float2* nxt = Tb;
  for (int k = 1; k <= 12; k++) {
    float2 acc = make_float2(0.f, 0.f);
    if (act) {
      int t_hi = (j + 2 < c - 1) ? j + 2 : c - 1;
      for (int t = t_lo; t <= t_hi; t++) {
        float2 xv = term[i*CUT + t], yv = Bm[t*CUT + j];
        acc.x += xv.x*yv.x - xv.y*yv.y;
        acc.y += xv.x*yv.y + xv.y*yv.x;
      }
      float inv = 1.0f/(float)k;
      acc.x *= inv; acc.y *= inv;
      nxt[i*CUT + j] = acc;
      Ot[i*CUT + j].x += acc.x;
      Ot[i*CUT + j].y += acc.y;
    }
    float2* z = term; term = nxt; nxt = z;
    __syncthreads();
  }
  for (int q = 0; q < 8; q++) {   // 8 squarings (2^8 scaling)
    float2 acc = make_float2(0.f, 0.f);
    if (act) {
      for (int t = 0; t < c; t++) {
        float2 xv = Ot[i*CUT + t], yv = Ot[t*CUT + j];
        acc.x += xv.x*yv.x - xv.y*yv.y;
        acc.y += xv.x*yv.y + xv.y*yv.x;
      }
    }
    __syncthreads();
    if (act) Ot[i*CUT + j] = acc;
    __syncthreads();
  }

  if (task < 648) {
    if (act) {
      int off = (s < CUT) ? s*(s+1)*(2*s+1)/6
                          : SECT - ((27-s)*(28-s)*(55-2*s))/6;
      g_bs[gid][off + i*c + j] = Ot[tid];   // row-major (R2 layout)
    }
  } else {
    int u = task - 648;
    int circ = u / 12, rem = u % 12;
    int l = rem / 6, w = (rem / 3) % 2, m = rem % 3;
    int pi = (circ*2 + l)*3 + m;
    double phase;
    if (w == 0) phase = (double)vph1[pi] * (double)j;                        // M1 = S * R(vph1)
    else        phase = (double)vph2[pi] * (double)j + (double)kk[pi]*(double)(i*i); // M2 = K*D*R(vph2)
    float cr = (float)cos(phase), ci = (float)sin(phase);
    float2 sv = Ot[tid];
    g_sng[u][tid] = make_float2(sv.x*cr - sv.y*ci, sv.x*ci + sv.y*cr);
  }
}

// ============ initial displacement vectors: coherent-state closed form ============
__global__ void __launch_bounds__(256) dvec_kernel(const float* __restrict__ x)
{
  int tid = blockIdx.x*blockDim.x + threadIdx.x;
  if (tid >= 1024*6) return;
  int b = tid / 6, colx = tid % 6, circ = colx / 3, m = colx % 3;
  double xv = (double)x[tid];
  double c = exp(-0.5 * xv * xv);
  #pragma unroll
  for (int n = 0; n < CUT; n++) {
    g_dvec[circ][b][m][n] = (float)c;
    c *= xv * rsqrt((double)(n + 1));
  }
}

// ================= main evolution: one CTA per (batch, circuit) =================
__device__ __forceinline__ void cmac(float2& acc, float2 w, float2 v) {
  acc.x = fmaf(w.x, v.x, fmaf(-w.y, v.y, acc.x));
  acc.y = fmaf(w.x, v.y, fmaf( w.y, v.x, acc.y));
}

__global__ void __launch_bounds__(NT, 4) evolve_kernel(float* __restrict__ out)
{
  __shared__ float2 sp[DIM];
  __shared__ float2 sg[SECT];
  __shared__ float  sd[3*CUT];
  __shared__ float  sred[3][NT/32];

  const int tid = threadIdx.x;
  const int b = blockIdx.x, circ = blockIdx.y;

  if (tid < 3*CUT) sd[tid] = g_dvec[circ][b][tid/CUT][tid%CUT];
  __syncthreads();
  for (int idx = tid; idx < DIM; idx += NT) {
    int i0 = idx / 196, j0 = (idx / CUT) % CUT, k0 = idx % CUT;
    sp[idx] = make_float2(sd[i0]*sd[CUT + j0]*sd[2*CUT + k0], 0.0f);
  }

  // ---- BS job decode: 392 jobs = (sector cell) x (fiber half of 7) ----
  int s = 0, csz = 1, pm = 0, gbase = 0, row = 0, col = 0, r0 = 0;
  const bool bs_act = (tid < 392);
  if (bs_act) {
    int jj = tid, cum = 0, ss = 0;
    for (ss = 0; ss < 27; ss++) {
      int cc = (ss < CUT) ? ss + 1 : 27 - ss;
      if (jj < cum + 2*cc) break;
      cum += 2*cc;
    }
    s   = ss;
    csz = (s < CUT) ? s + 1 : 27 - s;
    pm  = (s < CUT) ? 0 : s - 13;
    int q = jj - cum;
    int half = q / csz;
    int idxs = q % csz;
    r0  = half * 7;
    row = pm + idxs; col = s - row;
    int off = (s < CUT) ? s*(s+1)*(2*s+1)/6 : SECT - ((27-s)*(28-s)*(55-2*s))/6;
    gbase = off + idxs*csz;
  }
  const int in01 = (pm*13 + s)*CUT;         // mode01 input base (u stride 182)
  const int ob01 = (row*CUT + col)*CUT;     // mode01 output base
  const int in12 = pm*13 + s;               // mode12 input base (u stride 13)
  const int ob12 = row*CUT + col;           // mode12 output cell (i stride 196)

  const int m1s[3] = {0, 1, 0};   // PAIRS = [(0,1),(1,2),(0,1)]
  for (int l = 0; l < 2; l++) {
    for (int half_ = 0; half_ < 2; half_++) {
      // ---- 3 beamsplitter gates ----
      for (int p = 0; p < 3; p++) {
        const float2* gm = g_bs[(circ*2 + l)*6 + half_*3 + p];
        for (int ii = tid; ii < SECT; ii += NT) sg[ii] = gm[ii];
        __syncthreads();
        float2 acc[7];
        if (bs_act) {
          #pragma unroll
          for (int r = 0; r < 7; r++) acc[r] = make_float2(0.f, 0.f);
          if (m1s[p] == 0) {          // contract axes (0,1); fiber axis 2 (stride 1)
            for (int u = 0; u < csz; u++) {
              float2 w = sg[gbase + u];
              const float2* f = sp + in01 + u*182 + r0;
              #pragma unroll
              for (int r = 0; r < 7; r++) cmac(acc[r], w, f[r]);
            }
          } else {                    // contract axes (1,2); fiber axis 0 (stride 196)
            for (int u = 0; u < csz; u++) {
              float2 w = sg[gbase + u];
              const float2* f = sp + in12 + u*13 + r0*196;
              #pragma unroll
              for (int r = 0; r < 7; r++) cmac(acc[r], w, f[r*196]);
            }
          }
        }
        __syncthreads();
        if (bs_act) {
          if (m1s[p] == 0) {
            float2* o = sp + ob01 + r0;
            #pragma unroll
            for (int r = 0; r < 7; r++) o[r] = acc[r];
          } else {
            #pragma unroll
            for (int r = 0; r < 7; r++) sp[(r0 + r)*196 + ob12] = acc[r];
          }
        }
        // no trailing sync: next staging writes sg (disjoint from sp)
      }
      // ---- 3 combined single-mode gates: 392 jobs ----
      for (int m = 0; m < 3; m++) {
        const float2* gm = g_sng[(circ*2 + l)*6 + half_*3 + m];
        if (tid < 196) sg[tid] = gm[tid];
        __syncthreads();
        if (half_ == 0) {
          // M1 = S*R is exactly checkerboard: gate[a][t]==0 unless (a^t) even.
          // 392 jobs = (fiber f = tid>>1) x (parity P = tid&1): 7 in -> 7 out.
          float2 o[7];
          int base = 0, stride = 1;
          if (tid < 392) {
            int f = tid >> 1;
            int P = tid & 1;
            if (m == 0)      { base = f;                       stride = 196; }
            else if (m == 1) { base = (f/CUT)*196 + (f%CUT);   stride = CUT; }
            else             { base = f*CUT;                   stride = 1;   }
            base += P*stride;                  // parity offset folded into base
            float2 fb[7];
            const float2* src = sp + base;
            #pragma unroll
            for (int t = 0; t < 7; t++) fb[t] = src[2*t*stride];
            const float2* gr = sg + P*CUT + P; // gate[P+2a][P+2t]
            #pragma unroll
            for (int a = 0; a < 7; a++) {
              float2 acc2 = make_float2(0.f, 0.f);
              #pragma unroll
              for (int t = 0; t < 7; t++) cmac(acc2, gr[2*a*CUT + 2*t], fb[t]);
              o[a] = acc2;
            }
          }
          __syncthreads();
          if (tid < 392) {
            float2* dst = sp + base;
            #pragma unroll
            for (int a = 0; a < 7; a++) dst[2*a*stride] = o[a];
          }
        } else {
          // dense M2 = K*D*R: 392 jobs = (fiber f = tid>>1) x (output half h7)
          float2 o[7];
          int base = 0, stride = 1, h7 = 0;
          if (tid < 392) {
            int f = tid >> 1;
            h7 = (tid & 1) * 7;
            if (m == 0)      { base = f;                       stride = 196; }
            else if (m == 1) { base = (f/CUT)*196 + (f%CUT);   stride = CUT; }
            else             { base = f*CUT;                   stride = 1;   }
            float2 fb[CUT];
            #pragma unroll
            for (int t = 0; t < CUT; t++) fb[t] = sp[base + t*stride];
            #pragma unroll
            for (int a = 0; a < 7; a++) {
              float2 acc2 = make_float2(0.f, 0.f);
              #pragma unroll
              for (int t = 0; t < CUT; t++) cmac(acc2, sg[(h7 + a)*CUT + t], fb[t]);
              o[a] = acc2;
            }
          }
          __syncthreads();
          if (tid < 392) {
            #pragma unroll
            for (int a = 0; a < 7; a++) sp[base + (h7 + a)*stride] = o[a];
          }
        }
        // no trailing sync (next staging writes sg only)
      }
    }
  }
  __syncthreads();   // order final writeback before the expectation sweep

  // ---- expectations: single fused sweep for all 3 modes ----
  {
    float l0 = 0.f, l1 = 0.f, l2 = 0.f;
    for (int idx = tid; idx < DIM; idx += NT) {
      int i0 = idx / 196, rem = idx % 196;
      int j0 = rem / CUT, k0 = rem % CUT;
      float2 a2 = sp[idx];
      if (i0 < CUT-1) {
        float2 b2 = sp[idx + 196];
        l0 += sqrtf((float)(i0+1)) * (a2.x*b2.x + a2.y*b2.y);
      }
      if (j0 < CUT-1) {
        float2 b2 = sp[idx + CUT];
        l1 += sqrtf((float)(j0+1)) * (a2.x*b2.x + a2.y*b2.y);
      }
      if (k0 < CUT-1) {
        float2 b2 = sp[idx + 1];
        l2 += sqrtf((float)(k0+1)) * (a2.x*b2.x + a2.y*b2.y);
      }
    }
    #pragma unroll
    for (int o = 16; o > 0; o >>= 1) {
      l0 += __shfl_down_sync(0xffffffffu, l0, o);
      l1 += __shfl_down_sync(0xffffffffu, l1, o);
      l2 += __shfl_down_sync(0xffffffffu, l2, o);
    }
    if ((tid & 31) == 0) {
      sred[0][tid >> 5] = l0;
      sred[1][tid >> 5] = l1;
      sred[2][tid >> 5] = l2;
    }
    __syncthreads();
    if (tid < 3) {
      float tot = 0.f;
      #pragma unroll
      for (int w2 = 0; w2 < NT/32; w2++) tot += sred[tid][w2];
      out[b*6 + circ*3 + tid] = 2.f * tot;
    }
  }
}

// ================================ launch ================================
extern "C" void kernel_launch(void* const* d_in, const int* in_sizes, int n_in,
                              void* d_out, int out_size)
{
  (void)in_sizes; (void)n_in; (void)out_size;
  const float* x    = (const float*)d_in[0];
  const float* th1  = (const float*)d_in[1];
  const float* ph1  = (const float*)d_in[2];
  const float* vph1 = (const float*)d_in[3];
  const float* rr   = (const float*)d_in[4];
  const float* phr  = (const float*)d_in[5];
  const float* th2  = (const float*)d_in[6];
  const float* ph2  = (const float*)d_in[7];
  const float* vph2 = (const float*)d_in[8];
  const float* aa   = (const float*)d_in[9];
  const float* pha  = (const float*)d_in[10];
  const float* kk   = (const float*)d_in[11];

  gates_kernel<<<672, 196>>>(th1, ph1, vph1, rr, phr, th2, ph2, vph2, aa, pha, kk);
  dvec_kernel<<<24, 256>>>(x);
  dim3 grid(1024, 2);
  evolve_kernel<<<grid, NT>>>((float*)d_out);
}

// round 11
// speedup vs baseline: 2.1944x; 1.0305x over previous
#include <cuda_runtime.h>

#define CUT  14
#define DIM  2744          // 14^3
#define SECT 1834          // sum over sectors of c(s)^2
#define BSPAD 1840         // SECT padded to float4 multiple
#define NT   448           // evolve threads per CTA

// ---------------- persistent device scratch (no allocs allowed) ----------------
__device__ float  g_bsR[24][BSPAD];      // 24 BS gates: REAL sector-packed rotation R
__device__ float2 g_sng[24][CUT*CUT];    // 24 combined single-mode gates (phases absorbed)
__device__ float2 g_ph[24][CUT];         // per BS gate: e^{i n phi}, n=0..13
__device__ float  g_dvec[2][1024][3][CUT]; // initial displacement vectors (real)

// ---------------- packed f32x2 helpers ----------------
__device__ __forceinline__ unsigned long long pk2(float lo, float hi) {
  unsigned long long r;
  asm("mov.b64 %0, {%1, %2};" : "=l"(r) : "f"(lo), "f"(hi));
  return r;
}
__device__ __forceinline__ unsigned long long f2fma(unsigned long long a,
                                                    unsigned long long b,
                                                    unsigned long long c) {
  unsigned long long d;
  asm("fma.rn.f32x2 %0, %1, %2, %3;" : "=l"(d) : "l"(a), "l"(b), "l"(c));
  return d;
}

// ================= gate precompute: fp32 expm (s=8, terms=12, banded Taylor) =================
// BS gates now REAL: U = D exp(G) D^dag with G real antisymmetric; we exponentiate G
// and store R = exp(G) (real). Phases e^{i n phi} stored in g_ph; absorbed phases go
// into the M0 single-mode gates and the initial state.
__global__ void __launch_bounds__(196) gates_kernel(
    const float* __restrict__ th1, const float* __restrict__ ph1,
    const float* __restrict__ vph1, const float* __restrict__ rr,
    const float* __restrict__ phr, const float* __restrict__ th2,
    const float* __restrict__ ph2, const float* __restrict__ vph2,
    const float* __restrict__ aa, const float* __restrict__ pha,
    const float* __restrict__ kk)
{
  __shared__ float2 Bm[196], Ta[196], Tb[196], Ot[196];
  const int tid = threadIdx.x;
  const int i = tid / CUT, j = tid % CUT;
  const int task = blockIdx.x;

  int c = CUT, s = 0, pm = 0, gid = -1;
  double2 h = make_double2(0.0, 0.0);

  if (task < 648) {
    gid = task / 27; s = task % 27;
    pm = (s < CUT) ? 0 : s - (CUT-1);
    c  = (s < CUT) ? s + 1 : 2*CUT - 1 - s;
    int circ = gid / 12, rem = gid % 12;
    int l = rem / 6, w = (rem / 3) % 2, p = rem % 3;
    int pi = (circ*2 + l)*3 + p;
    double th = (double)((w ? th2 : th1)[pi]);
    double ph = (double)((w ? ph2 : ph1)[pi]);
    // phase vector e^{i n phi} (once per gate, via the s==0 task)
    if (s == 0 && tid < CUT) {
      double a = (double)tid * ph;
      g_ph[gid][tid] = make_float2((float)cos(a), (float)sin(a));
    }
    if (i < c && j < c) {
      int P = pm + i, Q = s - P;
      if (j == i - 1) {            // G[i][i-1] = theta*sqrt(P*(Q+1))  (real)
        h.x = th * sqrt((double)P * (double)(Q + 1));
      } else if (j == i + 1) {     // G[i][i+1] = -theta*sqrt((P+1)*Q) (real)
        h.x = -th * sqrt((double)(P + 1) * (double)Q);
      }
    }
  } else {
    int u = task - 648;
    int circ = u / 12, rem = u % 12;
    int l = rem / 6, w = (rem / 3) % 2, m = rem % 3;
    int pi = (circ*2 + l)*3 + m;
    if (w == 0) {  // squeeze
      double rv = (double)rr[pi], pv = (double)phr[pi];
      double zr = rv*cos(pv), zi = rv*sin(pv);
      if (j == i + 2) {
        double mag = 0.5*sqrt((double)(i+1)*(double)(i+2));
        h.x = mag*zr; h.y = -mag*zi;
      } else if (i == j + 2) {
        double mag = 0.5*sqrt((double)(j+1)*(double)(j+2));
        h.x = -mag*zr; h.y = -mag*zi;
      }
    } else {       // disp
      double av = (double)aa[pi], pv = (double)pha[pi];
      double ar = av*cos(pv), ai = av*sin(pv);
      if (i == j + 1) {
        double mag = sqrt((double)(j+1));
        h.x = mag*ar; h.y = mag*ai;
      } else if (j == i + 1) {
        double mag = sqrt((double)(i+1));
        h.x = -mag*ar; h.y = mag*ai;
      }
    }
  }

  const bool act = (i < c && j < c);
  const double sc = 1.0/256.0;   // 2^-8
  Bm[tid] = make_float2((float)(h.x*sc), (float)(h.y*sc));
  float idv = (act && i == j) ? 1.0f : 0.0f;
  Ta[tid] = make_float2(idv, 0.0f);
  Ot[tid] = make_float2(idv, 0.0f);
  __syncthreads();

  const int t_lo = (j >= 2) ? j - 2 : 0;
  float2* term = Ta; float2* nxt = Tb;
  for (int k = 1; k <= 12; k++) {
    float2 acc = make_float2(0.f, 0.f);
    if (act) {
      int t_hi = (j + 2 < c - 1) ? j + 2 : c - 1;
      for (int t = t_lo; t <= t_hi; t++) {
        float2 xv = term[i*CUT + t], yv = Bm[t*CUT + j];
        acc.x += xv.x*yv.x - xv.y*yv.y;
        acc.y += xv.x*yv.y + xv.y*yv.x;
      }
      float inv = 1.0f/(float)k;
      acc.x *= inv; acc.y *= inv;
      nxt[i*CUT + j] = acc;
      Ot[i*CUT + j].x += acc.x;
      Ot[i*CUT + j].y += acc.y;
    }
    float2* z = term; term = nxt; nxt = z;
    __syncthreads();
  }
  for (int q = 0; q < 8; q++) {   // 8 squarings (2^8 scaling)
    float2 acc = make_float2(0.f, 0.f);
    if (act) {
      for (int t = 0; t < c; t++) {
        float2 xv = Ot[i*CUT + t], yv = Ot[t*CUT + j];
        acc.x += xv.x*yv.x - xv.y*yv.y;
        acc.y += xv.x*yv.y + xv.y*yv.x;
      }
    }
    __syncthreads();
    if (act) Ot[i*CUT + j] = acc;
    __syncthreads();
  }

  if (task < 648) {
    if (act) {
      int off = (s < CUT) ? s*(s+1)*(2*s+1)/6
                          : SECT - ((27-s)*(28-s)*(55-2*s))/6;
      g_bsR[gid][off + i*c + j] = Ot[tid].x;   // real rotation
    }
  } else {
    int u = task - 648;
    int circ = u / 12, rem = u % 12;
    int l = rem / 6, w = (rem / 3) % 2, m = rem % 3;
    int pi = (circ*2 + l)*3 + m;
    double phase;
    if (w == 0) phase = (double)vph1[pi] * (double)j;                        // M1 = S * R(vph1)
    else        phase = (double)vph2[pi] * (double)j + (double)kk[pi]*(double)(i*i); // M2 = K*D*R(vph2)
    if (m == 0) {
      // absorb BS phase diagonals on mode 0:
      //   column phase +j*phi2 of THIS half, row phase -i*phi0 of the NEXT half
      double phcol = (double)((w ? ph2 : ph1)[(circ*2 + l)*3 + 2]);
      double phrow = 0.0;
      if (!(l == 1 && w == 1)) {
        int ln = (w == 0) ? l : l + 1;
        int wn = (w == 0) ? 1 : 0;
        phrow = (double)((wn ? ph2 : ph1)[(circ*2 + ln)*3 + 0]);
      }
      phase += (double)j * phcol - (double)i * phrow;
    }
    float cr = (float)cos(phase), ci = (float)sin(phase);
    float2 sv = Ot[tid];
    g_sng[u][tid] = make_float2(sv.x*cr - sv.y*ci, sv.x*ci + sv.y*cr);
  }
}

// ============ initial displacement vectors: coherent-state closed form ============
__global__ void __launch_bounds__(256) dvec_kernel(const float* __restrict__ x)
{
  int tid = blockIdx.x*blockDim.x + threadIdx.x;
  if (tid >= 1024*6) return;
  int b = tid / 6, colx = tid % 6, circ = colx / 3, m = colx % 3;
  double xv = (double)x[tid];
  double c = exp(-0.5 * xv * xv);
  #pragma unroll
  for (int n = 0; n < CUT; n++) {
    g_dvec[circ][b][m][n] = (float)c;
    c *= xv * rsqrt((double)(n + 1));
  }
}

// ================= main evolution: one CTA per (batch, circuit) =================
__device__ __forceinline__ void cmac(float2& acc, float2 w, float2 v) {
  acc.x = fmaf(w.x, v.x, fmaf(-w.y, v.y, acc.x));
  acc.y = fmaf(w.x, v.y, fmaf( w.y, v.x, acc.y));
}

__global__ void __launch_bounds__(NT, 4) evolve_kernel(float* __restrict__ out)
{
  __shared__ unsigned long long spl[DIM];       // state, (re,im) packed
  __shared__ alignas(16) float sgr[BSPAD];      // staged REAL BS gate
  __shared__ float2 sgm[196];                   // staged single-mode gate
  __shared__ float2 Tb[196], Tc[196];           // fused diagonal-phase tables
  __shared__ float2 ph0s[CUT];                  // init absorbed phase
  __shared__ float  sd[3*CUT];
  __shared__ float  sred[3][NT/32];

  float2* sp = (float2*)spl;
  const int tid = threadIdx.x;
  const int b = blockIdx.x, circ = blockIdx.y;

  if (tid < 3*CUT) sd[tid] = g_dvec[circ][b][tid/CUT][tid%CUT];
  if (tid >= 3*CUT && tid < 4*CUT) ph0s[tid - 3*CUT] = g_ph[circ*12][tid - 3*CUT];
  __syncthreads();
  // init with absorbed D0(phi0_{0,0})^dag : multiply by e^{-i n0 phi0}
  for (int idx = tid; idx < DIM; idx += NT) {
    int i0 = idx / 196, j0 = (idx / CUT) % CUT, k0 = idx % CUT;
    float prod = sd[i0]*sd[CUT + j0]*sd[2*CUT + k0];
    float2 p0 = ph0s[i0];
    sp[idx] = make_float2(prod*p0.x, -prod*p0.y);
  }

  // ---- BS job decode: 392 jobs = (sector cell) x (fiber half of 7) ----
  int s = 0, csz = 1, pm = 0, gbase = 0, row = 0, col = 0, r0 = 0;
  const bool bs_act = (tid < 392);
  if (bs_act) {
    int jj = tid, cum = 0, ss = 0;
    for (ss = 0; ss < 27; ss++) {
      int cc = (ss < CUT) ? ss + 1 : 27 - ss;
      if (jj < cum + 2*cc) break;
      cum += 2*cc;
    }
    s   = ss;
    csz = (s < CUT) ? s + 1 : 27 - s;
    pm  = (s < CUT) ? 0 : s - 13;
    int q = jj - cum;
    int half = q / csz;
    int idxs = q % csz;
    r0  = half * 7;
    row = pm + idxs; col = s - row;
    int off = (s < CUT) ? s*(s+1)*(2*s+1)/6 : SECT - ((27-s)*(28-s)*(55-2*s))/6;
    gbase = off + idxs*csz;
  }
  const int in01 = (pm*13 + s)*CUT;         // mode01 input base (u stride 182)
  const int ob01 = (row*CUT + col)*CUT;     // mode01 output base
  const int in12 = pm*13 + s;               // mode12 input base (u stride 13)
  const int ob12 = row*CUT + col;           // mode12 output cell (i stride 196)

  const int m1s[3] = {0, 1, 0};   // PAIRS = [(0,1),(1,2),(0,1)]
  for (int l = 0; l < 2; l++) {
    for (int half_ = 0; half_ < 2; half_++) {
      const int gidbase = (circ*2 + l)*6 + half_*3;

      // =================== three REAL beamsplitter rotations ===================
      for (int p = 0; p < 3; p++) {
        // stage real gate; on p==0 also build both phase tables
        {
          const float4* gm4 = (const float4*)g_bsR[gidbase + p];
          float4* sg4 = (float4*)sgr;
          for (int ii = tid; ii < BSPAD/4; ii += NT) sg4[ii] = gm4[ii];
          if (p == 0) {
            if (tid < 196) {
              float2 a = g_ph[gidbase + 0][tid/CUT], bb = g_ph[gidbase + 1][tid%CUT];
              // a * conj(b)
              Tb[tid] = make_float2(a.x*bb.x + a.y*bb.y, a.y*bb.x - a.x*bb.y);
            } else if (tid < 392) {
              int e = tid - 196;
              float2 a = g_ph[gidbase + 2][e/CUT], bb = g_ph[gidbase + 1][e%CUT];
              // conj(a) * b
              Tc[e] = make_float2(a.x*bb.x + a.y*bb.y, a.x*bb.y - a.y*bb.x);
            }
          }
        }
        __syncthreads();
        unsigned long long acc[7];
        if (bs_act) {
          #pragma unroll
          for (int r = 0; r < 7; r++) acc[r] = 0ull;
          if (m1s[p] == 0) {          // contract axes (0,1); fiber axis 2 (stride 1)
            for (int u = 0; u < csz; u++) {
              float w = sgr[gbase + u];
              unsigned long long wp = pk2(w, w);
              const unsigned long long* f = spl + in01 + u*182 + r0;
              #pragma unroll
              for (int r = 0; r < 7; r++) acc[r] = f2fma(wp, f[r], acc[r]);
            }
          } else {                    // contract axes (1,2); fiber axis 0 (stride 196)
            for (int u = 0; u < csz; u++) {
              float w = sgr[gbase + u];
              unsigned long long wp = pk2(w, w);
              const unsigned long long* f = spl + in12 + u*13 + r0*196;
              #pragma unroll
              for (int r = 0; r < 7; r++) acc[r] = f2fma(wp, f[r*196], acc[r]);
            }
          }
        }
        __syncthreads();
        if (bs_act) {
          if (m1s[p] == 0) {
            unsigned long long* o = spl + ob01 + r0;
            #pragma unroll
            for (int r = 0; r < 7; r++) o[r] = acc[r];
          } else {
            #pragma unroll
            for (int r = 0; r < 7; r++) spl[(r0 + r)*196 + ob12] = acc[r];
          }
        }
        __syncthreads();
        // fused diagonal sweeps between the rotations:
        //   after p0: Phi_b = D0(phi0) * D1(phi1)^dag ; after p1: Phi_c = D1(phi1) * D0(phi2)^dag
        if (p < 2) {
          const float2* T = (p == 0) ? Tb : Tc;
          for (int idx = tid; idx < DIM; idx += NT) {
            int n0 = idx / 196, n1 = (idx / CUT) % CUT;
            float2 t = T[n0*CUT + n1];
            float2 a = sp[idx];
            sp[idx] = make_float2(t.x*a.x - t.y*a.y, t.x*a.y + t.y*a.x);
          }
          __syncthreads();
        }
        // (trailing D0(phi2) after p2 is absorbed into the M0 gate below;
        //  leading D0(phi0)^dag of the next half is absorbed into this half's M0)
      }
      // ---- 3 combined single-mode gates: 392 jobs ----
      for (int m = 0; m < 3; m++) {
        const float2* gm = g_sng[(circ*2 + l)*6 + half_*3 + m];
        if (tid < 196) sgm[tid] = gm[tid];
        __syncthreads();
        if (half_ == 0) {
          // M1 = S*R checkerboard (phase absorption preserves the zeros)
          float2 o[7];
          int base = 0, stride = 1;
          if (tid < 392) {
            int f = tid >> 1;
            int P = tid & 1;
            if (m == 0)      { base = f;                       stride = 196; }
            else if (m == 1) { base = (f/CUT)*196 + (f%CUT);   stride = CUT; }
            else             { base = f*CUT;                   stride = 1;   }
            base += P*stride;
            float2 fb[7];
            const float2* src = sp + base;
            #pragma unroll
            for (int t = 0; t < 7; t++) fb[t] = src[2*t*stride];
            const float2* gr = sgm + P*CUT + P;
            #pragma unroll
            for (int a = 0; a < 7; a++) {
              float2 acc2 = make_float2(0.f, 0.f);
              #pragma unroll
              for (int t = 0; t < 7; t++) cmac(acc2, gr[2*a*CUT + 2*t], fb[t]);
              o[a] = acc2;
            }
          }
          __syncthreads();
          if (tid < 392) {
            float2* dst = sp + base;
            #pragma unroll
            for (int a = 0; a < 7; a++) dst[2*a*stride] = o[a];
          }
        } else {
          // dense M2 = K*D*R
          float2 o[7];
          int base = 0, stride = 1, h7 = 0;
          if (tid < 392) {
            int f = tid >> 1;
            h7 = (tid & 1) * 7;
            if (m == 0)      { base = f;                       stride = 196; }
            else if (m == 1) { base = (f/CUT)*196 + (f%CUT);   stride = CUT; }
            else             { base = f*CUT;                   stride = 1;   }
            float2 fb[CUT];
            #pragma unroll
            for (int t = 0; t < CUT; t++) fb[t] = sp[base + t*stride];
            #pragma unroll
            for (int a = 0; a < 7; a++) {
              float2 acc2 = make_float2(0.f, 0.f);
              #pragma unroll
              for (int t = 0; t < CUT; t++) cmac(acc2, sgm[(h7 + a)*CUT + t], fb[t]);
              o[a] = acc2;
            }
          }
          __syncthreads();
          if (tid < 392) {
            #pragma unroll
            for (int a = 0; a < 7; a++) sp[base + (h7 + a)*stride] = o[a];
          }
        }
        // no trailing sync (next staging writes sgm only)
      }
    }
  }
  __syncthreads();   // order final writeback before the expectation sweep

  // ---- expectations: single fused sweep for all 3 modes ----
  {
    float l0 = 0.f, l1 = 0.f, l2 = 0.f;
    for (int idx = tid; idx < DIM; idx += NT) {
      int i0 = idx / 196, rem = idx % 196;
      int j0 = rem / CUT, k0 = rem % CUT;
      float2 a2 = sp[idx];
      if (i0 < CUT-1) {
        float2 b2 = sp[idx + 196];
        l0 += sqrtf((float)(i0+1)) * (a2.x*b2.x + a2.y*b2.y);
      }
      if (j0 < CUT-1) {
        float2 b2 = sp[idx + CUT];
        l1 += sqrtf((float)(j0+1)) * (a2.x*b2.x + a2.y*b2.y);
      }
      if (k0 < CUT-1) {
        float2 b2 = sp[idx + 1];
        l2 += sqrtf((float)(k0+1)) * (a2.x*b2.x + a2.y*b2.y);
      }
    }
    #pragma unroll
    for (int o = 16; o > 0; o >>= 1) {
      l0 += __shfl_down_sync(0xffffffffu, l0, o);
      l1 += __shfl_down_sync(0xffffffffu, l1, o);
      l2 += __shfl_down_sync(0xffffffffu, l2, o);
    }
    if ((tid & 31) == 0) {
      sred[0][tid >> 5] = l0;
      sred[1][tid >> 5] = l1;
      sred[2][tid >> 5] = l2;
    }
    __syncthreads();
    if (tid < 3) {
      float tot = 0.f;
      #pragma unroll
      for (int w2 = 0; w2 < NT/32; w2++) tot += sred[tid][w2];
      out[b*6 + circ*3 + tid] = 2.f * tot;
    }
  }
}

// ================================ launch ================================
extern "C" void kernel_launch(void* const* d_in, const int* in_sizes, int n_in,
                              void* d_out, int out_size)
{
  (void)in_sizes; (void)n_in; (void)out_size;
  const float* x    = (const float*)d_in[0];
  const float* th1  = (const float*)d_in[1];
  const float* ph1  = (const float*)d_in[2];
  const float* vph1 = (const float*)d_in[3];
  const float* rr   = (const float*)d_in[4];
  const float* phr  = (const float*)d_in[5];
  const float* th2  = (const float*)d_in[6];
  const float* ph2  = (const float*)d_in[7];
  const float* vph2 = (const float*)d_in[8];
  const float* aa   = (const float*)d_in[9];
  const float* pha  = (const float*)d_in[10];
  const float* kk   = (const float*)d_in[11];

  gates_kernel<<<672, 196>>>(th1, ph1, vph1, rr, phr, th2, ph2, vph2, aa, pha, kk);
  dvec_kernel<<<24, 256>>>(x);
  dim3 grid(1024, 2);
  evolve_kernel<<<grid, NT>>>((float*)d_out);
}